// round 15
// baseline (speedup 1.0000x reference)
#include <cuda_runtime.h>
#include <cuda_bf16.h>

// CRF loss, linear-domain scan — bf16 inner dot, fwd/bwd split, 3 CTAs/SM.
// grid = 444 (3 CTAs/SM exactly): bids 0..255 FORWARD row bid (t=1..692);
// bids 256..443 BACKWARD rows (bid-256)+188k (t=1023 init, 330 scaled steps
// down to t=693, final plain matvec -> B_692). Join: Z = sum_j A692*B692.
// E = exp(trans) and alpha are bf16 (HFMA2); emission multipliers, renorm
// (exact power-of-2 from exponent of alpha[0]), gold score, logs stay f32/f64.

namespace {
constexpr int TT = 128;
constexpr int SS = 1024;
constexpr int NB = 256;
constexpr int NBWD = 188;
constexpr int GRID = NB + NBWD;  // 444 = 3 * 148
constexpr int START_TAG = 126;
constexpr int END_TAG = 127;
}

typedef unsigned int u32;
__device__ float g_avec[NB][TT];
__device__ float g_bvec[NB][TT];
__device__ int g_lea[NB];
__device__ int g_leb[NB];
__device__ float g_gold[NB];
__device__ double g_part[NB];
__device__ unsigned int g_cnt[NB];
__device__ unsigned int g_ticket;

__device__ __forceinline__ __nv_bfloat162 u2bf2(u32 x) {
    __nv_bfloat162 r;
    *reinterpret_cast<u32*>(&r) = x;
    return r;
}

// bf16 dot of shared alpha (128 bf16 = 16 x LDS.128) with this thread's
// 64 bf16x2 E pairs; 8 bf16x2 accumulators, f32 finish.
__device__ __forceinline__ float dotrow(const uint4* __restrict__ ap,
                                        const __nv_bfloat162* __restrict__ E) {
    __nv_bfloat162 acc[8];
#pragma unroll
    for (int i = 0; i < 8; i++) acc[i] = u2bf2(0u);
#pragma unroll
    for (int k = 0; k < 16; k++) {
        uint4 q = ap[k];
        acc[(4 * k + 0) & 7] = __hfma2(u2bf2(q.x), E[4 * k + 0], acc[(4 * k + 0) & 7]);
        acc[(4 * k + 1) & 7] = __hfma2(u2bf2(q.y), E[4 * k + 1], acc[(4 * k + 1) & 7]);
        acc[(4 * k + 2) & 7] = __hfma2(u2bf2(q.z), E[4 * k + 2], acc[(4 * k + 2) & 7]);
        acc[(4 * k + 3) & 7] = __hfma2(u2bf2(q.w), E[4 * k + 3], acc[(4 * k + 3) & 7]);
    }
    acc[0] = __hadd2(acc[0], acc[4]);
    acc[1] = __hadd2(acc[1], acc[5]);
    acc[2] = __hadd2(acc[2], acc[6]);
    acc[3] = __hadd2(acc[3], acc[7]);
    acc[0] = __hadd2(acc[0], acc[2]);
    acc[1] = __hadd2(acc[1], acc[3]);
    acc[0] = __hadd2(acc[0], acc[1]);
    float2 f = __bfloat1622float2(acc[0]);
    return f.x + f.y;
}

__device__ __forceinline__ void crf_step(const __nv_bfloat16* __restrict__ ar,
                                         __nv_bfloat16* __restrict__ aw,
                                         const __nv_bfloat162* __restrict__ E,
                                         float expem, int j) {
    float v = dotrow(reinterpret_cast<const uint4*>(ar), E) * expem;
    aw[j] = __float2bfloat16_rn(v);
    __syncthreads();
}

// Group-top renorm scale from exponent of alpha[0] (bf16 exponent field ==
// f32 exponent field). Exact power-of-2; le absorbs it. Clamped for safety.
__device__ __forceinline__ float topscale(const __nv_bfloat16* __restrict__ ar,
                                          int& le) {
    unsigned short bits = *reinterpret_cast<const unsigned short*>(ar);
    int ex = (int)((bits >> 7) & 0xffu) - 127;
    ex = max(-100, min(100, ex));
    le += ex;
    return __int_as_float((127 - ex) << 23);
}

// Per-row join (second arriver reduces); last row triggers the global mean.
__device__ __forceinline__ void join_row(int r, float mTE, int j,
                                         float* red, float* out) {
    __shared__ int sjoin, sfinal;
    __threadfence();
    __syncthreads();
    if (j == 0) sjoin = (atomicAdd(&g_cnt[r], 1u) == 1u) ? 1 : 0;
    __syncthreads();
    if (!sjoin) return;
    __threadfence();
    float p = __ldcg(&g_avec[r][j]) * __ldcg(&g_bvec[r][j]);
#pragma unroll
    for (int o = 16; o > 0; o >>= 1)
        p += __shfl_xor_sync(0xffffffffu, p, o);
    if ((j & 31) == 0) red[j >> 5] = p;
    __syncthreads();
    if (j == 0) {
        float s = red[0] + red[1] + red[2] + red[3];
        int lt = __ldcg(&g_lea[r]) + __ldcg(&g_leb[r]);
        double part = (double)lt * 0.6931471805599453 + (double)mTE +
                      log((double)s) - (double)__ldcg(&g_gold[r]);
        g_part[r] = part;
        g_cnt[r] = 0;
        __threadfence();
        sfinal = (atomicAdd(&g_ticket, 1u) == NB - 1) ? 1 : 0;
    }
    __syncthreads();
    if (sfinal) {
        __threadfence();
        double d = __ldcg(&g_part[j]) + __ldcg(&g_part[j + 128]);
#pragma unroll
        for (int o = 16; o > 0; o >>= 1)
            d += __shfl_xor_sync(0xffffffffu, d, o);
        __shared__ double sd[4];
        if ((j & 31) == 0) sd[j >> 5] = d;
        __syncthreads();
        if (j == 0) {
            out[0] = (float)((sd[0] + sd[1] + sd[2] + sd[3]) * (1.0 / NB));
            g_ticket = 0;  // reset for graph replay
        }
    }
    __syncthreads();
}

__global__ void __launch_bounds__(128, 3)
crf_kernel(const float* __restrict__ em, const int* __restrict__ tags,
           const float* __restrict__ trans, float* __restrict__ out) {
    const int bid = blockIdx.x;
    const int j = threadIdx.x;
    __shared__ __align__(16) __nv_bfloat16 alpha[2][TT];
    __shared__ __align__(16) float red[8];

    const bool isFwd = (bid < NB);

    // E pairs in bf16x2: fwd thread j owns column j (pairs over i);
    // bwd thread j owns row j (pairs over k) for the transposed matvec.
    __nv_bfloat162 E[64];
    if (isFwd) {
#pragma unroll
        for (int k = 0; k < 64; k++)
            E[k] = __floats2bfloat162_rn(__expf(trans[(2 * k) * TT + j]),
                                         __expf(trans[(2 * k + 1) * TT + j]));
    } else {
#pragma unroll
        for (int k = 0; k < 64; k++)
            E[k] = __floats2bfloat162_rn(__expf(trans[j * TT + 2 * k]),
                                         __expf(trans[j * TT + 2 * k + 1]));
    }

    // one-time: max of END transition row
    float tE = trans[END_TAG * TT + j];
    {
        float m = tE;
#pragma unroll
        for (int o = 16; o > 0; o >>= 1)
            m = fmaxf(m, __shfl_xor_sync(0xffffffffu, m, o));
        if ((j & 31) == 0) red[j >> 5] = m;
    }
    __syncthreads();
    const float mTE = fmaxf(fmaxf(red[0], red[1]), fmaxf(red[2], red[3]));
    __syncthreads();

    if (isFwd) {
        // ================ FORWARD: row bid, t = 1..692 ================
        const int r = bid;
        const float* emb = em + (size_t)r * SS * TT;
        const int* tg = tags + r * SS;

        // gold path score (full row, fp32 exact)
        float gold = 0.f;
#pragma unroll
        for (int q = 0; q < SS / TT; q++) {
            int s = q * TT + j;
            int cur = tg[s];
            int prev = (s == 0) ? START_TAG : tg[s - 1];
            gold += emb[s * TT + cur] + trans[prev * TT + cur];
        }
        if (j == 0) gold += trans[tg[SS - 1] * TT + END_TAG];

        alpha[0][j] = __float2bfloat16_rn((j == START_TAG) ? 1.f : 0.f);
        __syncthreads();

        int le = 0;
        float b0 = emb[1 * TT + j];
        float b1 = emb[2 * TT + j];
        float b2 = emb[3 * TT + j];
        float b3 = emb[4 * TT + j];
        __nv_bfloat16* a0p = alpha[0];
        __nv_bfloat16* a1p = alpha[1];

        // group 0 (t = 1..4): sc = 1 (alpha one-hot)
        {
            float e0 = __expf(b0);
            float e1 = __expf(b1);
            float e2 = __expf(b2);
            float e3 = __expf(b3);
            const float* pe = emb + (size_t)5 * TT + j;
            float n0 = pe[0 * TT];
            float n1 = pe[1 * TT];
            float n2 = pe[2 * TT];
            float n3 = pe[3 * TT];
            crf_step(a0p, a1p, E, e0, j);
            crf_step(a1p, a0p, E, e1, j);
            crf_step(a0p, a1p, E, e2, j);
            crf_step(a1p, a0p, E, e3, j);
            b0 = n0; b1 = n1; b2 = n2; b3 = n3;
        }
        // groups 1..171 (t = 5..688) with prefetch
#pragma unroll 1
        for (int g = 1; g < 172; g++) {
            float sc = topscale(a0p, le);
            float e0 = __expf(b0) * sc;
            float e1 = __expf(b1);
            float e2 = __expf(b2);
            float e3 = __expf(b3);
            const float* pe = emb + (size_t)(4 * g + 5) * TT + j;
            float n0 = pe[0 * TT];
            float n1 = pe[1 * TT];
            float n2 = pe[2 * TT];
            float n3 = pe[3 * TT];
            crf_step(a0p, a1p, E, e0, j);
            crf_step(a1p, a0p, E, e1, j);
            crf_step(a0p, a1p, E, e2, j);
            crf_step(a1p, a0p, E, e3, j);
            b0 = n0; b1 = n1; b2 = n2; b3 = n3;
        }
        // group 172 (t = 689..692), no prefetch
        {
            float sc = topscale(a0p, le);
            float e0 = __expf(b0) * sc;
            float e1 = __expf(b1);
            float e2 = __expf(b2);
            float e3 = __expf(b3);
            crf_step(a0p, a1p, E, e0, j);
            crf_step(a1p, a0p, E, e1, j);
            crf_step(a0p, a1p, E, e2, j);
            crf_step(a1p, a0p, E, e3, j);
        }
        // A_692 in alpha[0]
        g_avec[r][j] = __bfloat162float(a0p[j]);

        float y = gold;
#pragma unroll
        for (int o = 16; o > 0; o >>= 1)
            y += __shfl_xor_sync(0xffffffffu, y, o);
        if ((j & 31) == 0) red[4 + (j >> 5)] = y;
        __syncthreads();
        if (j == 0) {
            g_gold[r] = red[4] + red[5] + red[6] + red[7];
            g_lea[r] = le;
        }
        join_row(r, mTE, j, red, out);
    } else {
        // ========= BACKWARD: rows (bid-256)+188k, t = 1023..693 =========
#pragma unroll 1
        for (int r = bid - NB; r < NB; r += NBWD) {
            const float* emb = em + (size_t)r * SS * TT;
            __syncthreads();
            // B~_1023[j] = exp(em_1023[j] + tE[j] - mTE)
            alpha[0][j] = __float2bfloat16_rn(__expf(emb[1023 * TT + j] + tE - mTE));
            __syncthreads();

            int le = 0;
            float b0 = emb[1022 * TT + j];
            float b1 = emb[1021 * TT + j];
            float b2 = emb[1020 * TT + j];
            float b3 = emb[1019 * TT + j];
            __nv_bfloat16* a0p = alpha[0];
            __nv_bfloat16* a1p = alpha[1];

            // group 0 (t = 1022..1019): sc = 1
            {
                float e0 = __expf(b0);
                float e1 = __expf(b1);
                float e2 = __expf(b2);
                float e3 = __expf(b3);
                const float* pe = emb + (size_t)1018 * TT + j;
                float n0 = pe[0];
                float n1 = pe[-1 * TT];
                float n2 = pe[-2 * TT];
                float n3 = pe[-3 * TT];
                crf_step(a0p, a1p, E, e0, j);
                crf_step(a1p, a0p, E, e1, j);
                crf_step(a0p, a1p, E, e2, j);
                crf_step(a1p, a0p, E, e3, j);
                b0 = n0; b1 = n1; b2 = n2; b3 = n3;
            }
            // groups 1..80 (t = 1018..699) with prefetch
#pragma unroll 1
            for (int g = 1; g < 81; g++) {
                float sc = topscale(a0p, le);
                float e0 = __expf(b0) * sc;
                float e1 = __expf(b1);
                float e2 = __expf(b2);
                float e3 = __expf(b3);
                const float* pe = emb + (size_t)(1018 - 4 * g) * TT + j;
                float n0 = pe[0];
                float n1 = pe[-1 * TT];
                float n2 = pe[-2 * TT];
                float n3 = pe[-3 * TT];
                crf_step(a0p, a1p, E, e0, j);
                crf_step(a1p, a0p, E, e1, j);
                crf_step(a0p, a1p, E, e2, j);
                crf_step(a1p, a0p, E, e3, j);
                b0 = n0; b1 = n1; b2 = n2; b3 = n3;
            }
            // group 81 (t = 698..695), prefetch remainder t = 694, 693
            float m0 = emb[694 * TT + j];
            float m1 = emb[693 * TT + j];
            {
                float sc = topscale(a0p, le);
                float e0 = __expf(b0) * sc;
                float e1 = __expf(b1);
                float e2 = __expf(b2);
                float e3 = __expf(b3);
                crf_step(a0p, a1p, E, e0, j);
                crf_step(a1p, a0p, E, e1, j);
                crf_step(a0p, a1p, E, e2, j);
                crf_step(a1p, a0p, E, e3, j);
            }
            // remainder (t = 694, 693)
            {
                float sc = topscale(a0p, le);
                crf_step(a0p, a1p, E, __expf(m0) * sc, j);
                crf_step(a1p, a0p, E, __expf(m1), j);
            }
            // B~_693 in alpha[0]; final plain matvec: B_692 = E * B~_693
            float v = dotrow(reinterpret_cast<const uint4*>(a0p), E);
            g_bvec[r][j] = v;
            if (j == 0) g_leb[r] = le;

            join_row(r, mTE, j, red, out);
        }
    }
}

extern "C" void kernel_launch(void* const* d_in, const int* in_sizes, int n_in,
                              void* d_out, int out_size) {
    const float* em = (const float*)d_in[0];     // [256,1024,128] f32
    const int* tags = (const int*)d_in[1];       // [256,1024] i32
    const float* trans = (const float*)d_in[2];  // [128,128] f32
    crf_kernel<<<GRID, 128>>>(em, tags, trans, (float*)d_out);
}